// round 6
// baseline (speedup 1.0000x reference)
#include <cuda_runtime.h>
#include <cuda_bf16.h>

#define TPB    256
#define NBLK   888             // 148 SMs * 6 CTAs
#define NQ     10
#define EPSF   1e-12f
#define L2E    1.4426950408889634f
#define MAXPTS 2048

__device__ float2       g_partials[NBLK];
__device__ unsigned int g_sem = 0;   // self-resetting via atomicInc wrap

__device__ __forceinline__ float fsqrt_approx(float s) {
    float d; asm("sqrt.approx.f32 %0, %1;" : "=f"(d) : "f"(s)); return d;
}
__device__ __forceinline__ float fex2_approx(float a) {
    float e; asm("ex2.approx.f32 %0, %1;" : "=f"(e) : "f"(a)); return e;
}

// ---- shared epilogue: block reduce + last-block global reduce ----
__device__ __forceinline__ void block_and_grid_reduce(
    float acc_d, float acc_e, float beta, float t0, float tn,
    int n_events, float* __restrict__ out)
{
    #pragma unroll
    for (int o = 16; o > 0; o >>= 1) {
        acc_d += __shfl_down_sync(0xffffffffu, acc_d, o);
        acc_e += __shfl_down_sync(0xffffffffu, acc_e, o);
    }
    __shared__ float2 wred[TPB / 32];
    if ((threadIdx.x & 31) == 0)
        wred[threadIdx.x >> 5] = make_float2(acc_d, acc_e);
    __syncthreads();

    __shared__ bool is_last;
    if (threadIdx.x == 0) {
        float sd = 0.0f, se = 0.0f;
        #pragma unroll
        for (int w = 0; w < TPB / 32; w++) { sd += wred[w].x; se += wred[w].y; }
        g_partials[blockIdx.x] = make_float2(sd, se);
        __threadfence();
        unsigned old = atomicInc(&g_sem, gridDim.x - 1);
        is_last = (old == gridDim.x - 1);
    }
    __syncthreads();

    if (is_last) {
        double sd = 0.0, se = 0.0;
        const volatile float2* gp = (const volatile float2*)g_partials;
        for (int i = threadIdx.x; i < (int)gridDim.x; i += TPB) {
            sd += (double)gp[i].x;
            se += (double)gp[i].y;
        }
        #pragma unroll
        for (int o = 16; o > 0; o >>= 1) {
            sd += __shfl_down_sync(0xffffffffu, sd, o);
            se += __shfl_down_sync(0xffffffffu, se, o);
        }
        __shared__ double2 dred[TPB / 32];
        if ((threadIdx.x & 31) == 0)
            dred[threadIdx.x >> 5] = make_double2(sd, se);
        __syncthreads();
        if (threadIdx.x == 0) {
            double tsd = 0.0, tse = 0.0;
            #pragma unroll
            for (int w = 0; w < TPB / 32; w++) { tsd += dred[w].x; tse += dred[w].y; }
            double dtqD = ((double)tn - (double)t0) / (double)NQ;
            out[0] = (float)((double)beta * (double)n_events - tsd - dtqD * tse);
        }
    }
}

// ---- event term ----
__device__ __forceinline__ float event_sum(
    const float4* __restrict__ sm,
    const int2* __restrict__ data_uv, const float* __restrict__ data_t,
    int n_events, int tid, int stride)
{
    float acc_d = 0.0f;
    const int4*   uv4 = (const int4*)data_uv;
    const float2* tt2 = (const float2*)data_t;
    const int nev2 = n_events >> 1;
    for (int i = tid; i < nev2; i += stride) {
        int4   q  = uv4[i];
        float2 tt = tt2[i];
        float4 a0 = sm[q.x], b0 = sm[q.y];
        float4 a1 = sm[q.z], b1 = sm[q.w];
        float dx0 = fmaf(a0.z - b0.z, tt.x, a0.x - b0.x);
        float dy0 = fmaf(a0.w - b0.w, tt.x, a0.y - b0.y);
        float dx1 = fmaf(a1.z - b1.z, tt.y, a1.x - b1.x);
        float dy1 = fmaf(a1.w - b1.w, tt.y, a1.y - b1.y);
        acc_d += fsqrt_approx(fmaf(dx0, dx0, fmaf(dy0, dy0, EPSF)));
        acc_d += fsqrt_approx(fmaf(dx1, dx1, fmaf(dy1, dy1, EPSF)));
    }
    if ((n_events & 1) && tid == 0) {
        int   i = n_events - 1;
        int2  uv = data_uv[i];
        float t  = data_t[i];
        float4 a = sm[uv.x], b = sm[uv.y];
        float dx = fmaf(a.z - b.z, t, a.x - b.x);
        float dy = fmaf(a.w - b.w, t, a.y - b.y);
        acc_d += fsqrt_approx(fmaf(dx, dx, fmaf(dy, dy, EPSF)));
    }
    return acc_d;
}

// ================= structured kernel: pairs computed from k =================
__global__ __launch_bounds__(TPB, 6) void cvm_struct_kernel(
    const float* __restrict__ z0, const float* __restrict__ v0,
    const float* __restrict__ beta_p, const float* __restrict__ data_t,
    const float* __restrict__ t0_p, const float* __restrict__ tn_p,
    const int2* __restrict__ data_uv,
    int n_points, int n_events, int n_pairs,
    float* __restrict__ out)
{
    __shared__ float4 sm[MAXPTS];
    {
        const float2* z2 = (const float2*)z0;
        const float2* v2 = (const float2*)v0;
        for (int i = threadIdx.x; i < n_points; i += TPB) {
            float2 z = z2[i];
            float2 v = v2[i];
            sm[i] = make_float4(z.x, z.y, v.x, v.y);
        }
    }
    __syncthreads();

    const float beta = *beta_p;
    const float t0   = *t0_p;
    const float tn   = *tn_p;
    const float dtq  = (tn - t0) * (1.0f / NQ);
    const float t05  = t0 + 0.5f * dtq;
    const float bL2E = beta * L2E;

    // quadrature abscissae, hoisted once (k-invariant)
    float tq[NQ];
    #pragma unroll
    for (int q = 0; q < NQ; q++) tq[q] = fmaf((float)q, dtq, t05);

    const int stride = gridDim.x * TPB;
    const int tid    = blockIdx.x * TPB + threadIdx.x;

    float acc_d = event_sum(sm, data_uv, data_t, n_events, tid, stride);

    float acc_e0 = 0.0f, acc_e1 = 0.0f;
    for (int k = tid; k < n_pairs; k += stride) {
        // invert linear tril index: i = row, j = col (i > j)
        float r = fsqrt_approx(fmaf(8.0f, (float)k, 1.0f));
        int i   = (int)(0.5f * (1.0f + r));
        int tri = (i * (i - 1)) >> 1;
        if (k < tri)            { i--; tri -= i; }
        else if (k >= tri + i)  { tri += i; i++; }
        int j = k - tri;

        float4 a = sm[i];   // mostly warp-uniform (broadcast)
        float4 b = sm[j];   // consecutive across lanes (conflict-free)
        float dx0 = a.x - b.x, dy0 = a.y - b.y;
        float dvx = a.z - b.z, dvy = a.w - b.w;
        // |dz(t)|^2 = c0 + c1*t + c2*t^2  (eps folded into c0).
        // NOTE: evaluated by cancellation -> can round negative near
        // collisions; MUST clamp before sqrt (R4 NaN bug).
        float c0 = fmaf(dx0, dx0, fmaf(dy0, dy0, EPSF));
        float c1 = 2.0f * fmaf(dx0, dvx, dy0 * dvy);
        float c2 = fmaf(dvx, dvx, dvy * dvy);
        #pragma unroll
        for (int q = 0; q < NQ; q++) {
            float t  = tq[q];
            float s  = fmaf(fmaf(c2, t, c1), t, c0);
            s        = fmaxf(s, EPSF);            // clamp: no NaN from sqrt
            float d  = fsqrt_approx(s);
            float e  = fex2_approx(fmaf(d, -L2E, bL2E));
            if (q & 1) acc_e1 += e; else acc_e0 += e;
        }
    }

    block_and_grid_reduce(acc_d, acc_e0 + acc_e1, beta, t0, tn, n_events, out);
}

// ================= fallback kernel: gather from pair_u/pair_v ===============
__global__ __launch_bounds__(TPB, 6) void cvm_gather_kernel(
    const float* __restrict__ z0, const float* __restrict__ v0,
    const float* __restrict__ beta_p, const float* __restrict__ data_t,
    const float* __restrict__ t0_p, const float* __restrict__ tn_p,
    const int2* __restrict__ data_uv,
    const int* __restrict__ pair_u, const int* __restrict__ pair_v,
    int n_points, int n_events, int n_pairs,
    float* __restrict__ out)
{
    __shared__ float4 sm[MAXPTS];
    {
        const float2* z2 = (const float2*)z0;
        const float2* v2 = (const float2*)v0;
        for (int i = threadIdx.x; i < n_points; i += TPB) {
            float2 z = z2[i];
            float2 v = v2[i];
            sm[i] = make_float4(z.x, z.y, v.x, v.y);
        }
    }
    __syncthreads();

    const float beta = *beta_p;
    const float t0   = *t0_p;
    const float tn   = *tn_p;
    const float dtq  = (tn - t0) * (1.0f / NQ);
    const float t05  = t0 + 0.5f * dtq;
    const float bL2E = beta * L2E;

    float tq[NQ];
    #pragma unroll
    for (int q = 0; q < NQ; q++) tq[q] = fmaf((float)q, dtq, t05);

    const int stride = gridDim.x * TPB;
    const int tid    = blockIdx.x * TPB + threadIdx.x;

    float acc_d = event_sum(sm, data_uv, data_t, n_events, tid, stride);

    float acc_e0 = 0.0f, acc_e1 = 0.0f;
    for (int k = tid; k < n_pairs; k += stride) {
        float4 a = sm[pair_u[k]];
        float4 b = sm[pair_v[k]];
        float dx0 = a.x - b.x, dy0 = a.y - b.y;
        float dvx = a.z - b.z, dvy = a.w - b.w;
        float c0 = fmaf(dx0, dx0, fmaf(dy0, dy0, EPSF));
        float c1 = 2.0f * fmaf(dx0, dvx, dy0 * dvy);
        float c2 = fmaf(dvx, dvx, dvy * dvy);
        #pragma unroll
        for (int q = 0; q < NQ; q++) {
            float t  = tq[q];
            float s  = fmaf(fmaf(c2, t, c1), t, c0);
            s        = fmaxf(s, EPSF);            // clamp: no NaN from sqrt
            float d  = fsqrt_approx(s);
            float e  = fex2_approx(fmaf(d, -L2E, bL2E));
            if (q & 1) acc_e1 += e; else acc_e0 += e;
        }
    }

    block_and_grid_reduce(acc_d, acc_e0 + acc_e1, beta, t0, tn, n_events, out);
}

extern "C" void kernel_launch(void* const* d_in, const int* in_sizes, int n_in,
                              void* d_out, int out_size)
{
    // metadata order: z0, v0, beta, data_t, t0, tn, data_uv, pair_u, pair_v
    const float* z0      = (const float*)d_in[0];
    const float* v0      = (const float*)d_in[1];
    const float* beta_p  = (const float*)d_in[2];
    const float* data_t  = (const float*)d_in[3];
    const float* t0_p    = (const float*)d_in[4];
    const float* tn_p    = (const float*)d_in[5];
    const int2*  data_uv = (const int2*)d_in[6];
    const int*   pair_u  = (const int*)d_in[7];
    const int*   pair_v  = (const int*)d_in[8];
    float* out = (float*)d_out;

    int n_points = in_sizes[0] / 2;
    int n_events = in_sizes[3];
    int n_pairs  = in_sizes[7];

    long long full = (long long)n_points * (n_points - 1) / 2;
    if (n_points <= MAXPTS && full == (long long)n_pairs) {
        cvm_struct_kernel<<<NBLK, TPB>>>(z0, v0, beta_p, data_t, t0_p, tn_p,
                                         data_uv, n_points, n_events, n_pairs, out);
    } else {
        cvm_gather_kernel<<<NBLK, TPB>>>(z0, v0, beta_p, data_t, t0_p, tn_p,
                                         data_uv, pair_u, pair_v,
                                         n_points, n_events, n_pairs, out);
    }
}

// round 7
// speedup vs baseline: 1.1488x; 1.1488x over previous
#include <cuda_runtime.h>
#include <cuda_bf16.h>

#define TPB    256
#define NBLK   592             // 148 SMs * 4 CTAs (R2-proven config)
#define NQ     10
#define EPSF   1e-12f
#define L2E    1.4426950408889634f
#define MAXPTS 2048

__device__ float2       g_partials[NBLK];
__device__ unsigned int g_sem = 0;   // self-resetting via atomicInc wrap

__device__ __forceinline__ float fsqrt_approx(float s) {
    float d; asm("sqrt.approx.f32 %0, %1;" : "=f"(d) : "f"(s)); return d;
}
__device__ __forceinline__ float fex2_approx(float a) {
    float e; asm("ex2.approx.f32 %0, %1;" : "=f"(e) : "f"(a)); return e;
}

// ---- shared epilogue: block reduce + last-block global reduce ----
__device__ __forceinline__ void block_and_grid_reduce(
    float acc_d, float acc_e, float beta, float t0, float tn,
    int n_events, float* __restrict__ out)
{
    #pragma unroll
    for (int o = 16; o > 0; o >>= 1) {
        acc_d += __shfl_down_sync(0xffffffffu, acc_d, o);
        acc_e += __shfl_down_sync(0xffffffffu, acc_e, o);
    }
    __shared__ float2 wred[TPB / 32];
    if ((threadIdx.x & 31) == 0)
        wred[threadIdx.x >> 5] = make_float2(acc_d, acc_e);
    __syncthreads();

    __shared__ bool is_last;
    if (threadIdx.x == 0) {
        float sd = 0.0f, se = 0.0f;
        #pragma unroll
        for (int w = 0; w < TPB / 32; w++) { sd += wred[w].x; se += wred[w].y; }
        g_partials[blockIdx.x] = make_float2(sd, se);
        __threadfence();
        unsigned old = atomicInc(&g_sem, gridDim.x - 1);
        is_last = (old == gridDim.x - 1);
    }
    __syncthreads();

    if (is_last) {
        double sd = 0.0, se = 0.0;
        const volatile float2* gp = (const volatile float2*)g_partials;
        for (int i = threadIdx.x; i < (int)gridDim.x; i += TPB) {
            sd += (double)gp[i].x;
            se += (double)gp[i].y;
        }
        #pragma unroll
        for (int o = 16; o > 0; o >>= 1) {
            sd += __shfl_down_sync(0xffffffffu, sd, o);
            se += __shfl_down_sync(0xffffffffu, se, o);
        }
        __shared__ double2 dred[TPB / 32];
        if ((threadIdx.x & 31) == 0)
            dred[threadIdx.x >> 5] = make_double2(sd, se);
        __syncthreads();
        if (threadIdx.x == 0) {
            double tsd = 0.0, tse = 0.0;
            #pragma unroll
            for (int w = 0; w < TPB / 32; w++) { tsd += dred[w].x; tse += dred[w].y; }
            double dtqD = ((double)tn - (double)t0) / (double)NQ;
            out[0] = (float)((double)beta * (double)n_events - tsd - dtqD * tse);
        }
    }
}

// ---- event term (2 events / iter) ----
__device__ __forceinline__ float event_sum(
    const float4* __restrict__ sm,
    const int2* __restrict__ data_uv, const float* __restrict__ data_t,
    int n_events, int tid, int stride)
{
    float acc_d = 0.0f;
    const int4*   uv4 = (const int4*)data_uv;
    const float2* tt2 = (const float2*)data_t;
    const int nev2 = n_events >> 1;
    for (int i = tid; i < nev2; i += stride) {
        int4   q  = uv4[i];
        float2 tt = tt2[i];
        float4 a0 = sm[q.x], b0 = sm[q.y];
        float4 a1 = sm[q.z], b1 = sm[q.w];
        float dx0 = fmaf(a0.z - b0.z, tt.x, a0.x - b0.x);
        float dy0 = fmaf(a0.w - b0.w, tt.x, a0.y - b0.y);
        float dx1 = fmaf(a1.z - b1.z, tt.y, a1.x - b1.x);
        float dy1 = fmaf(a1.w - b1.w, tt.y, a1.y - b1.y);
        acc_d += fsqrt_approx(fmaf(dx0, dx0, fmaf(dy0, dy0, EPSF)));
        acc_d += fsqrt_approx(fmaf(dx1, dx1, fmaf(dy1, dy1, EPSF)));
    }
    if ((n_events & 1) && tid == 0) {
        int   i = n_events - 1;
        int2  uv = data_uv[i];
        float t  = data_t[i];
        float4 a = sm[uv.x], b = sm[uv.y];
        float dx = fmaf(a.z - b.z, t, a.x - b.x);
        float dy = fmaf(a.w - b.w, t, a.y - b.y);
        acc_d += fsqrt_approx(fmaf(dx, dx, fmaf(dy, dy, EPSF)));
    }
    return acc_d;
}

// ============ gather kernel: 2 pairs/iter, quadratic form + clamp ============
__global__ __launch_bounds__(TPB, 4) void cvm_gather_kernel(
    const float* __restrict__ z0, const float* __restrict__ v0,
    const float* __restrict__ beta_p, const float* __restrict__ data_t,
    const float* __restrict__ t0_p, const float* __restrict__ tn_p,
    const int2* __restrict__ data_uv,
    const int* __restrict__ pair_u, const int* __restrict__ pair_v,
    int n_points, int n_events, int n_pairs,
    float* __restrict__ out)
{
    __shared__ float4 sm[MAXPTS];
    {
        const float2* z2 = (const float2*)z0;
        const float2* v2 = (const float2*)v0;
        for (int i = threadIdx.x; i < n_points; i += TPB) {
            float2 z = z2[i];
            float2 v = v2[i];
            sm[i] = make_float4(z.x, z.y, v.x, v.y);
        }
    }
    __syncthreads();

    const float beta = *beta_p;
    const float t0   = *t0_p;
    const float tn   = *tn_p;
    const float dtq  = (tn - t0) * (1.0f / NQ);
    const float t05  = t0 + 0.5f * dtq;
    const float bL2E = beta * L2E;

    // quadrature abscissae, hoisted (k-invariant)
    float tq[NQ];
    #pragma unroll
    for (int q = 0; q < NQ; q++) tq[q] = fmaf((float)q, dtq, t05);

    const int stride = NBLK * TPB;
    const int tid    = blockIdx.x * TPB + threadIdx.x;

    float acc_d = event_sum(sm, data_uv, data_t, n_events, tid, stride);

    float eA0 = 0.0f, eA1 = 0.0f, eB0 = 0.0f, eB1 = 0.0f;
    {
        const int2* pu2 = (const int2*)pair_u;
        const int2* pv2 = (const int2*)pair_v;
        const int np2 = n_pairs >> 1;
        for (int i = tid; i < np2; i += stride) {
            int2 uu = pu2[i];
            int2 vv = pv2[i];
            float4 a0 = sm[uu.x], b0 = sm[vv.x];
            float4 a1 = sm[uu.y], b1 = sm[vv.y];

            // pair A: |dz(t)|^2 = cA0 + cA1 t + cA2 t^2 (eps in cA0)
            float dxA = a0.x - b0.x, dyA = a0.y - b0.y;
            float vxA = a0.z - b0.z, vyA = a0.w - b0.w;
            float cA0 = fmaf(dxA, dxA, fmaf(dyA, dyA, EPSF));
            float cA1 = 2.0f * fmaf(dxA, vxA, dyA * vyA);
            float cA2 = fmaf(vxA, vxA, vyA * vyA);
            // pair B
            float dxB = a1.x - b1.x, dyB = a1.y - b1.y;
            float vxB = a1.z - b1.z, vyB = a1.w - b1.w;
            float cB0 = fmaf(dxB, dxB, fmaf(dyB, dyB, EPSF));
            float cB1 = 2.0f * fmaf(dxB, vxB, dyB * vyB);
            float cB2 = fmaf(vxB, vxB, vyB * vyB);

            #pragma unroll
            for (int q = 0; q < NQ; q++) {
                float t  = tq[q];
                float sA = fmaf(fmaf(cA2, t, cA1), t, cA0);
                float sB = fmaf(fmaf(cB2, t, cB1), t, cB0);
                sA = fmaxf(sA, EPSF);             // cancellation guard (R4 NaN bug)
                sB = fmaxf(sB, EPSF);
                float dA = fsqrt_approx(sA);
                float dB = fsqrt_approx(sB);
                float eA = fex2_approx(fmaf(dA, -L2E, bL2E));
                float eB = fex2_approx(fmaf(dB, -L2E, bL2E));
                if (q & 1) { eA1 += eA; eB1 += eB; }
                else       { eA0 += eA; eB0 += eB; }
            }
        }
        if ((n_pairs & 1) && tid == 0) {
            int k = n_pairs - 1;
            float4 a = sm[pair_u[k]], b = sm[pair_v[k]];
            float dx = a.x - b.x, dy = a.y - b.y;
            float vx = a.z - b.z, vy = a.w - b.w;
            float c0 = fmaf(dx, dx, fmaf(dy, dy, EPSF));
            float c1 = 2.0f * fmaf(dx, vx, dy * vy);
            float c2 = fmaf(vx, vx, vy * vy);
            #pragma unroll
            for (int q = 0; q < NQ; q++) {
                float t = tq[q];
                float s = fmaxf(fmaf(fmaf(c2, t, c1), t, c0), EPSF);
                float d = fsqrt_approx(s);
                eA0 += fex2_approx(fmaf(d, -L2E, bL2E));
            }
        }
    }

    block_and_grid_reduce(acc_d, (eA0 + eA1) + (eB0 + eB1),
                          beta, t0, tn, n_events, out);
}

extern "C" void kernel_launch(void* const* d_in, const int* in_sizes, int n_in,
                              void* d_out, int out_size)
{
    // metadata order: z0, v0, beta, data_t, t0, tn, data_uv, pair_u, pair_v
    const float* z0      = (const float*)d_in[0];
    const float* v0      = (const float*)d_in[1];
    const float* beta_p  = (const float*)d_in[2];
    const float* data_t  = (const float*)d_in[3];
    const float* t0_p    = (const float*)d_in[4];
    const float* tn_p    = (const float*)d_in[5];
    const int2*  data_uv = (const int2*)d_in[6];
    const int*   pair_u  = (const int*)d_in[7];
    const int*   pair_v  = (const int*)d_in[8];
    float* out = (float*)d_out;

    int n_points = in_sizes[0] / 2;
    int n_events = in_sizes[3];
    int n_pairs  = in_sizes[7];

    cvm_gather_kernel<<<NBLK, TPB>>>(z0, v0, beta_p, data_t, t0_p, tn_p,
                                     data_uv, pair_u, pair_v,
                                     n_points, n_events, n_pairs, out);
}